// round 2
// baseline (speedup 1.0000x reference)
#include <cuda_runtime.h>
#include <cuda_bf16.h>

// Problem constants
#define Bv  2
#define Hv  16
#define Sv  2048
#define DKv 64

// Tiling
#define BM 64          // queries per block
#define BN 64          // keys per tile
#define LD 68          // padded smem row stride (floats), 272B: 16B-aligned, conflict-breaking
#define NTHREADS 256

#define SMEM_FLOATS (4 * BM * LD)          // sQ, sKt, sV, sP
#define SMEM_BYTES  (SMEM_FLOATS * 4)      // 69632 bytes

// Fast exp on the FMA pipe (avoids MUFU throughput wall).
// Valid for x <= 0 (softmax args). Clamps to 2^-126 for very negative x.
__device__ __forceinline__ float fexp(float x) {
    float y = x * 1.4426950408889634f;          // log2(e)
    y = fmaxf(y, -126.0f);
    const float magic = 12582912.0f;            // 1.5 * 2^23
    float t = y + magic;                        // round-to-nearest in low bits
    int   n = __float_as_int(t) - 0x4B400000;   // integer part
    float f = y - (t - magic);                  // frac in [-0.5, 0.5]
    // 2^f via Taylor in f*ln2, |err| < 3e-6
    float p = 1.33336498e-3f;
    p = fmaf(p, f, 9.61011695e-3f);
    p = fmaf(p, f, 5.55036483e-2f);
    p = fmaf(p, f, 2.40226507e-1f);
    p = fmaf(p, f, 6.93147182e-1f);
    p = fmaf(p, f, 1.0f);
    return p * __int_as_float((n + 127) << 23);
}

__global__ __launch_bounds__(NTHREADS, 2)
void sdp_flash_kernel(const float* __restrict__ Q,
                      const float* __restrict__ K,
                      const float* __restrict__ V,
                      const float* __restrict__ Mask,
                      float* __restrict__ Out) {
    extern __shared__ float sm[];
    float* sQ  = sm;                 // [BM][LD]  row = query, col = dk
    float* sKt = sQ  + BM * LD;      // [DK][LD]  row = dk,    col = key   (transposed!)
    float* sV  = sKt + DKv * LD;     // [BN][LD]  row = key,   col = dk
    float* sP  = sV  + BN * LD;      // [BM][LD]  row = query, col = key

    const int tid = threadIdx.x;
    const int tx  = tid & 15;        // 0..15 -> 4 cols each
    const int ty  = tid >> 4;        // 0..15 -> 4 rows each
    const int tx4 = tx * 4;
    const int ty4 = ty * 4;

    const int h  = blockIdx.y;
    const int b  = blockIdx.z;
    const int q0 = blockIdx.x * BM;

    const size_t bh = (size_t)(b * Hv + h);
    const float* Qg  = Q + (bh * Sv + q0) * DKv;
    const float* Kg0 = K + bh * Sv * DKv;
    const float* Vg0 = V + bh * Sv * DKv;
    const float* Mg  = Mask + ((size_t)b * Sv + q0) * Sv;   // mask[b,0,q,:]

    // ---- Load Q tile once: [64 rows][64 dk], natural layout ----
    {
        const int r0 = tid >> 4;          // 0..15
        const int d4 = (tid & 15) * 4;    // 0..60
        #pragma unroll
        for (int r = 0; r < 4; r++) {
            const int row = r0 + r * 16;
            float4 v = *(const float4*)(Qg + row * DKv + d4);
            *(float4*)(sQ + row * LD + d4) = v;
        }
    }

    // Per-thread state: 4 query rows x 4 dk cols of O, plus row stats
    float o[4][4];
    float mrow[4], lrow[4];
    #pragma unroll
    for (int i = 0; i < 4; i++) {
        mrow[i] = -1e30f;
        lrow[i] = 0.0f;
        #pragma unroll
        for (int j = 0; j < 4; j++) o[i][j] = 0.0f;
    }

    const float scale = 0.125f;   // 1/sqrt(64)

    for (int kt = 0; kt < Sv / BN; kt++) {
        const float* Kg = Kg0 + (size_t)kt * BN * DKv;
        const float* Vg = Vg0 + (size_t)kt * BN * DKv;

        __syncthreads();   // previous iteration's PV GEMM done before overwriting sKt/sV

        // ---- Load K (transposed into sKt) and V (natural) ----
        {
            const int r0 = tid >> 4;
            const int d4 = (tid & 15) * 4;
            #pragma unroll
            for (int r = 0; r < 4; r++) {
                const int key = r0 + r * 16;
                float4 kv = *(const float4*)(Kg + key * DKv + d4);
                sKt[(d4 + 0) * LD + key] = kv.x;
                sKt[(d4 + 1) * LD + key] = kv.y;
                sKt[(d4 + 2) * LD + key] = kv.z;
                sKt[(d4 + 3) * LD + key] = kv.w;
                float4 vv = *(const float4*)(Vg + key * DKv + d4);
                *(float4*)(sV + key * LD + d4) = vv;
            }
        }

        // ---- Mask tile straight to registers (L2-resident across the 16 heads) ----
        float mk[4][4];
        #pragma unroll
        for (int i = 0; i < 4; i++) {
            float4 mv = *(const float4*)(Mg + (size_t)(ty4 + i) * Sv + kt * BN + tx4);
            mk[i][0] = mv.x; mk[i][1] = mv.y; mk[i][2] = mv.z; mk[i][3] = mv.w;
        }

        __syncthreads();   // K/V tiles visible

        // ---- S = Q @ K^T  (4x4 register tile) ----
        float acc[4][4];
        #pragma unroll
        for (int i = 0; i < 4; i++)
            #pragma unroll
            for (int j = 0; j < 4; j++) acc[i][j] = 0.0f;

        #pragma unroll
        for (int k4 = 0; k4 < DKv; k4 += 4) {
            float qr[4][4];
            #pragma unroll
            for (int i = 0; i < 4; i++) {
                float4 qv = *(const float4*)(sQ + (ty4 + i) * LD + k4);
                qr[i][0] = qv.x; qr[i][1] = qv.y; qr[i][2] = qv.z; qr[i][3] = qv.w;
            }
            #pragma unroll
            for (int u = 0; u < 4; u++) {
                float4 kv = *(const float4*)(sKt + (k4 + u) * LD + tx4);
                #pragma unroll
                for (int i = 0; i < 4; i++) {
                    acc[i][0] = fmaf(qr[i][u], kv.x, acc[i][0]);
                    acc[i][1] = fmaf(qr[i][u], kv.y, acc[i][1]);
                    acc[i][2] = fmaf(qr[i][u], kv.z, acc[i][2]);
                    acc[i][3] = fmaf(qr[i][u], kv.w, acc[i][3]);
                }
            }
        }

        // ---- Non-standard masking + streaming softmax update ----
        #pragma unroll
        for (int i = 0; i < 4; i++) {
            // apply scale * mask, then keep only strictly positive
            float s0 = acc[i][0] * scale * mk[i][0];
            float s1 = acc[i][1] * scale * mk[i][1];
            float s2 = acc[i][2] * scale * mk[i][2];
            float s3 = acc[i][3] * scale * mk[i][3];
            s0 = (s0 > 0.0f) ? s0 : -10000.0f;
            s1 = (s1 > 0.0f) ? s1 : -10000.0f;
            s2 = (s2 > 0.0f) ? s2 : -10000.0f;
            s3 = (s3 > 0.0f) ? s3 : -10000.0f;

            // row max across this thread's 4 cols, then across the 16 tx lanes
            float tmax = fmaxf(fmaxf(s0, s1), fmaxf(s2, s3));
            #pragma unroll
            for (int off = 1; off < 16; off <<= 1)
                tmax = fmaxf(tmax, __shfl_xor_sync(0xffffffffu, tmax, off));

            const float m_new = fmaxf(mrow[i], tmax);
            const float alpha = fexp(mrow[i] - m_new);

            float p0 = fexp(s0 - m_new);
            float p1 = fexp(s1 - m_new);
            float p2 = fexp(s2 - m_new);
            float p3 = fexp(s3 - m_new);

            float tsum = (p0 + p1) + (p2 + p3);
            #pragma unroll
            for (int off = 1; off < 16; off <<= 1)
                tsum += __shfl_xor_sync(0xffffffffu, tsum, off);

            lrow[i] = lrow[i] * alpha + tsum;
            mrow[i] = m_new;

            o[i][0] *= alpha; o[i][1] *= alpha; o[i][2] *= alpha; o[i][3] *= alpha;

            float4 pv = make_float4(p0, p1, p2, p3);
            *(float4*)(sP + (ty4 + i) * LD + tx4) = pv;
        }

        __syncthreads();   // P tile visible

        // ---- O += P @ V ----
        #pragma unroll
        for (int k4 = 0; k4 < BN; k4 += 4) {
            float pr[4][4];
            #pragma unroll
            for (int i = 0; i < 4; i++) {
                float4 pv = *(const float4*)(sP + (ty4 + i) * LD + k4);
                pr[i][0] = pv.x; pr[i][1] = pv.y; pr[i][2] = pv.z; pr[i][3] = pv.w;
            }
            #pragma unroll
            for (int u = 0; u < 4; u++) {
                float4 vv = *(const float4*)(sV + (k4 + u) * LD + tx4);
                #pragma unroll
                for (int i = 0; i < 4; i++) {
                    o[i][0] = fmaf(pr[i][u], vv.x, o[i][0]);
                    o[i][1] = fmaf(pr[i][u], vv.y, o[i][1]);
                    o[i][2] = fmaf(pr[i][u], vv.z, o[i][2]);
                    o[i][3] = fmaf(pr[i][u], vv.w, o[i][3]);
                }
            }
        }
    }

    // ---- Epilogue: normalize and store ----
    float* Og = Out + (bh * Sv + q0) * DKv;
    #pragma unroll
    for (int i = 0; i < 4; i++) {
        const float inv = 1.0f / lrow[i];
        float4 r = make_float4(o[i][0] * inv, o[i][1] * inv, o[i][2] * inv, o[i][3] * inv);
        *(float4*)(Og + (ty4 + i) * DKv + tx4) = r;
    }
}

extern "C" void kernel_launch(void* const* d_in, const int* in_sizes, int n_in,
                              void* d_out, int out_size) {
    const float* Q = (const float*)d_in[0];
    const float* K = (const float*)d_in[1];
    const float* V = (const float*)d_in[2];
    const float* M = (const float*)d_in[3];
    float* Out = (float*)d_out;

    cudaFuncSetAttribute(sdp_flash_kernel,
                         cudaFuncAttributeMaxDynamicSharedMemorySize, SMEM_BYTES);

    dim3 grid(Sv / BM, Hv, Bv);   // 32 x 16 x 2 = 1024 CTAs
    sdp_flash_kernel<<<grid, NTHREADS, SMEM_BYTES>>>(Q, K, V, M, Out);
}

// round 4
// speedup vs baseline: 2.4006x; 2.4006x over previous
#include <cuda_runtime.h>
#include <cuda_bf16.h>
#include <cstdint>

#define Bv   2
#define Hv   16
#define Sv   2048
#define DKv  64
#define BHv  32
#define BM   64
#define BN   64
#define NITER (Sv/BN)
#define SCALE2 0.18033688011112042f   // (1/8)*log2(e)

#define NELEM ((size_t)BHv * Sv * DKv)   // 4,194,304

__device__ __align__(16) __nv_bfloat16 g_Qa[NELEM];
__device__ __align__(16) __nv_bfloat16 g_Qb[NELEM];
__device__ __align__(16) __nv_bfloat16 g_Qc[NELEM];
__device__ __align__(16) __nv_bfloat16 g_Ka[NELEM];
__device__ __align__(16) __nv_bfloat16 g_Kb[NELEM];
__device__ __align__(16) __nv_bfloat16 g_Kc[NELEM];
__device__ __align__(16) __nv_bfloat16 g_Vh[NELEM];
__device__ __align__(16) __nv_bfloat16 g_Vl[NELEM];

__device__ __forceinline__ uint32_t smem_u32(const void* p) {
    uint32_t a;
    asm("{ .reg .u64 t; cvta.to.shared.u64 t, %1; cvt.u32.u64 %0, t; }" : "=r"(a) : "l"(p));
    return a;
}

__device__ __forceinline__ void mma16816(float* d, const uint32_t* a, uint32_t b0, uint32_t b1) {
    asm volatile("mma.sync.aligned.m16n8k16.row.col.f32.bf16.bf16.f32 "
        "{%0,%1,%2,%3}, {%4,%5,%6,%7}, {%8,%9}, {%0,%1,%2,%3};"
        : "+f"(d[0]), "+f"(d[1]), "+f"(d[2]), "+f"(d[3])
        : "r"(a[0]), "r"(a[1]), "r"(a[2]), "r"(a[3]), "r"(b0), "r"(b1));
}
__device__ __forceinline__ void ldsm2(uint32_t& x, uint32_t& y, uint32_t addr) {
    asm volatile("ldmatrix.sync.aligned.m8n8.x2.shared.b16 {%0,%1}, [%2];"
                 : "=r"(x), "=r"(y) : "r"(addr));
}
__device__ __forceinline__ void ldsm2t(uint32_t& x, uint32_t& y, uint32_t addr) {
    asm volatile("ldmatrix.sync.aligned.m8n8.x2.trans.shared.b16 {%0,%1}, [%2];"
                 : "=r"(x), "=r"(y) : "r"(addr));
}
__device__ __forceinline__ uint32_t pack_bf(float hi, float lo) {
    uint32_t r;
    asm("cvt.rn.bf16x2.f32 %0, %1, %2;" : "=r"(r) : "f"(hi), "f"(lo));
    return r;
}
#define CPA(dst, src) asm volatile("cp.async.cg.shared.global [%0], [%1], 16;" :: "r"(dst), "l"(src) : "memory")

// p = (u>0) ? 2^u : 0 with u = s*SCALE2*m. Pure FMA-pipe exp (no MUFU).
__device__ __forceinline__ float pexp(float s, float m) {
    float u = s * SCALE2 * m;
    float t = u + 12582912.0f;                       // round-to-nearest int
    int   n = (__float_as_int(t) - 0x4B400000 + 127) << 23;
    float f = u - (t - 12582912.0f);                 // frac in [-0.5, 0.5]
    float p = 1.3343e-3f;
    p = fmaf(p, f, 9.6181e-3f);
    p = fmaf(p, f, 5.55041e-2f);
    p = fmaf(p, f, 2.40226507e-1f);
    p = fmaf(p, f, 6.93147182e-1f);
    p = fmaf(p, f, 1.0f);
    p *= __int_as_float(n);
    return (u > 0.0f) ? p : 0.0f;
}

// ---- prep: split Q/K 3-way, V 2-way; K/V written chunk-swizzled for ldmatrix ----
__global__ __launch_bounds__(256) void prep(const float* __restrict__ Q,
                                            const float* __restrict__ K,
                                            const float* __restrict__ V) {
    const uint32_t g = blockIdx.x * 256 + threadIdx.x;   // 16B-chunk index
    const uint32_t s = (g >> 3) & (Sv - 1);
    const int which = blockIdx.y;                         // 0:Q 1:K 2:V
    const float* src = which == 0 ? Q : which == 1 ? K : V;
    const float4 v0 = ((const float4*)src)[g * 2 + 0];
    const float4 v1 = ((const float4*)src)[g * 2 + 1];
    const float x[8] = {v0.x, v0.y, v0.z, v0.w, v1.x, v1.y, v1.z, v1.w};
    const uint32_t og = (which == 0) ? g : ((g & ~7u) | ((g & 7u) ^ (s & 7u)));

    if (which < 2) {
        uint4 ua, ub, uc;
        __nv_bfloat16* A = (__nv_bfloat16*)&ua;
        __nv_bfloat16* B = (__nv_bfloat16*)&ub;
        __nv_bfloat16* C = (__nv_bfloat16*)&uc;
#pragma unroll
        for (int e = 0; e < 8; e++) {
            __nv_bfloat16 a = __float2bfloat16_rn(x[e]);
            float r1 = x[e] - __bfloat162float(a);
            __nv_bfloat16 bb = __float2bfloat16_rn(r1);
            A[e] = a; B[e] = bb;
            C[e] = __float2bfloat16_rn(r1 - __bfloat162float(bb));
        }
        if (which == 0) { ((uint4*)g_Qa)[og] = ua; ((uint4*)g_Qb)[og] = ub; ((uint4*)g_Qc)[og] = uc; }
        else            { ((uint4*)g_Ka)[og] = ua; ((uint4*)g_Kb)[og] = ub; ((uint4*)g_Kc)[og] = uc; }
    } else {
        uint4 uh, ul;
        __nv_bfloat16* Hh = (__nv_bfloat16*)&uh;
        __nv_bfloat16* Ll = (__nv_bfloat16*)&ul;
#pragma unroll
        for (int e = 0; e < 8; e++) {
            __nv_bfloat16 h = __float2bfloat16_rn(x[e]);
            Hh[e] = h;
            Ll[e] = __float2bfloat16_rn(x[e] - __bfloat162float(h));
        }
        ((uint4*)g_Vh)[og] = uh; ((uint4*)g_Vl)[og] = ul;
    }
}

// ---- main: register-MMA flash attention ----
__global__ __launch_bounds__(128, 2)
void sdp_mma(const float* __restrict__ Mask, float* __restrict__ Out) {
    extern __shared__ char smem[];
    const uint32_t sbase = smem_u32(smem);

    const int tid  = threadIdx.x;
    const int lane = tid & 31, warp = tid >> 5;
    const int bh = blockIdx.y, q0 = blockIdx.x * BM, b = bh >> 4;
    const int lq  = lane >> 2;            // 0..7
    const int lc2 = (lane & 3) * 2;       // 0,2,4,6
    const int r1 = q0 + warp * 16 + lq, r2 = r1 + 8;

    // --- Q fragments, loaded once, straight from gmem ---
    uint32_t qf[3][4][4];
    {
        const __nv_bfloat16* qs[3] = {g_Qa, g_Qb, g_Qc};
#pragma unroll
        for (int sp = 0; sp < 3; sp++)
#pragma unroll
            for (int c = 0; c < 4; c++)
#pragma unroll
                for (int r = 0; r < 4; r++) {
                    int m = (r & 1) ? r2 : r1;
                    int k = c * 16 + ((r >> 1) << 3) + lc2;
                    qf[sp][c][r] = *(const uint32_t*)(qs[sp] + ((size_t)bh * Sv + m) * DKv + k);
                }
    }

    float O[8][4];
#pragma unroll
    for (int j = 0; j < 8; j++)
#pragma unroll
        for (int e = 0; e < 4; e++) O[j][e] = 0.0f;
    float lacc0 = 0.0f, lacc1 = 0.0f;

    const float* mp1 = Mask + ((size_t)b * Sv + r1) * Sv + lc2;
    const float* mp2 = Mask + ((size_t)b * Sv + r2) * Sv + lc2;

    const size_t gbyte0 = (size_t)(bh * Sv) * 128;   // bf16 row = 128 bytes
    const char* garr[5] = {(const char*)g_Ka + gbyte0, (const char*)g_Kb + gbyte0,
                           (const char*)g_Kc + gbyte0, (const char*)g_Vh + gbyte0,
                           (const char*)g_Vl + gbyte0};

    // prologue: tile 0 -> buf 0
#pragma unroll
    for (int a = 0; a < 5; a++)
#pragma unroll
        for (int i = 0; i < 4; i++) {
            uint32_t off = (uint32_t)(tid + i * 128) * 16;
            CPA(sbase + a * 8192 + off, garr[a] + off);
        }
    asm volatile("cp.async.commit_group;" ::: "memory");

    for (int t = 0; t < NITER; t++) {
        const int buf = t & 1;
        if (t + 1 < NITER) {
            const uint32_t sb = sbase + (buf ^ 1) * 40960;
            const size_t go = (size_t)(t + 1) * 8192;
#pragma unroll
            for (int a = 0; a < 5; a++)
#pragma unroll
                for (int i = 0; i < 4; i++) {
                    uint32_t off = (uint32_t)(tid + i * 128) * 16;
                    CPA(sb + a * 8192 + off, garr[a] + go + off);
                }
            asm volatile("cp.async.commit_group;" ::: "memory");
            asm volatile("cp.async.wait_group 1;" ::: "memory");
        } else {
            asm volatile("cp.async.wait_group 0;" ::: "memory");
        }
        __syncthreads();

        const uint32_t sK = sbase + buf * 40960;
        const uint32_t sV = sK + 24576;

        // ---- S = Q K^T via 6 split products ----
        float S[8][4];
#pragma unroll
        for (int j = 0; j < 8; j++)
#pragma unroll
            for (int e = 0; e < 4; e++) S[j][e] = 0.0f;

#pragma unroll
        for (int c = 0; c < 4; c++) {
            const int rowk = (lane & 7);
            const int chk  = 2 * c + ((lane >> 3) & 1);
#pragma unroll
            for (int j = 0; j < 8; j++) {
                const int row = 8 * j + rowk;
                const uint32_t off = (uint32_t)row * 128 + (uint32_t)((chk ^ (row & 7)) << 4);
                uint32_t ka0, ka1, kb0, kb1, kc0, kc1;
                ldsm2(ka0, ka1, sK + 0 * 8192 + off);
                ldsm2(kb0, kb1, sK + 1 * 8192 + off);
                ldsm2(kc0, kc1, sK + 2 * 8192 + off);
                mma16816(S[j], qf[0][c], ka0, ka1);   // aa
                mma16816(S[j], qf[1][c], ka0, ka1);   // ba
                mma16816(S[j], qf[2][c], ka0, ka1);   // ca
                mma16816(S[j], qf[0][c], kb0, kb1);   // ab
                mma16816(S[j], qf[1][c], kb0, kb1);   // bb
                mma16816(S[j], qf[0][c], kc0, kc1);   // ac
            }
        }

        // ---- masked softmax (no row max needed: kept scores > 0, dead = 0) ----
        const float* m1 = mp1 + t * BN;
        const float* m2 = mp2 + t * BN;
        uint32_t aph[8][2], apl[8][2];
#pragma unroll
        for (int f = 0; f < 8; f++) {
            float2 mA = *(const float2*)(m1 + 8 * f);
            float2 mB = *(const float2*)(m2 + 8 * f);
            float p0 = pexp(S[f][0], mA.x);
            float p1 = pexp(S[f][1], mA.y);
            float p2 = pexp(S[f][2], mB.x);
            float p3 = pexp(S[f][3], mB.y);
            lacc0 += p0 + p1;
            lacc1 += p2 + p3;
            uint32_t h0 = pack_bf(p1, p0);
            uint32_t h1 = pack_bf(p3, p2);
            aph[f][0] = h0; aph[f][1] = h1;
            float e0 = p0 - __uint_as_float(h0 << 16);
            float e1 = p1 - __uint_as_float(h0 & 0xFFFF0000u);
            float e2 = p2 - __uint_as_float(h1 << 16);
            float e3 = p3 - __uint_as_float(h1 & 0xFFFF0000u);
            apl[f][0] = pack_bf(e1, e0);
            apl[f][1] = pack_bf(e3, e2);
        }

        // ---- O += P V via 3 split products ----
#pragma unroll
        for (int c = 0; c < 4; c++) {
            uint32_t a_h[4] = {aph[2 * c][0], aph[2 * c][1], aph[2 * c + 1][0], aph[2 * c + 1][1]};
            uint32_t a_l[4] = {apl[2 * c][0], apl[2 * c][1], apl[2 * c + 1][0], apl[2 * c + 1][1]};
            const int rowv = 16 * c + (lane & 15);
#pragma unroll
            for (int j = 0; j < 8; j++) {
                const uint32_t offv = (uint32_t)rowv * 128 + (uint32_t)((j ^ (rowv & 7)) << 4);
                uint32_t vh0, vh1, vl0, vl1;
                ldsm2t(vh0, vh1, sV + 0    + offv);
                ldsm2t(vl0, vl1, sV + 8192 + offv);
                mma16816(O[j], a_h, vh0, vh1);   // Phi*Vh
                mma16816(O[j], a_h, vl0, vl1);   // Phi*Vl
                mma16816(O[j], a_l, vh0, vh1);   // Plo*Vh
            }
        }
        __syncthreads();   // all warps done with buf before it is refilled
    }

    // ---- epilogue: quad-reduce row sums, normalize, store ----
    lacc0 += __shfl_xor_sync(0xffffffffu, lacc0, 1);
    lacc0 += __shfl_xor_sync(0xffffffffu, lacc0, 2);
    lacc1 += __shfl_xor_sync(0xffffffffu, lacc1, 1);
    lacc1 += __shfl_xor_sync(0xffffffffu, lacc1, 2);
    const float li1 = 1.0f / lacc0;
    const float li2 = 1.0f / lacc1;

    float* o1 = Out + ((size_t)bh * Sv + r1) * DKv + lc2;
    float* o2 = Out + ((size_t)bh * Sv + r2) * DKv + lc2;
#pragma unroll
    for (int j = 0; j < 8; j++) {
        float2 w1 = make_float2(O[j][0] * li1, O[j][1] * li1);
        float2 w2 = make_float2(O[j][2] * li2, O[j][3] * li2);
        *(float2*)(o1 + 8 * j) = w1;
        *(float2*)(o2 + 8 * j) = w2;
    }
}

extern "C" void kernel_launch(void* const* d_in, const int* in_sizes, int n_in,
                              void* d_out, int out_size) {
    const float* Q = (const float*)d_in[0];
    const float* K = (const float*)d_in[1];
    const float* V = (const float*)d_in[2];
    const float* M = (const float*)d_in[3];
    float* Out = (float*)d_out;

    prep<<<dim3((unsigned)(NELEM / 8 / 256), 3), 256>>>(Q, K, V);

    cudaFuncSetAttribute(sdp_mma, cudaFuncAttributeMaxDynamicSharedMemorySize, 81920);
    sdp_mma<<<dim3(Sv / BM, BHv), 128, 81920>>>(M, Out);
}

// round 5
// speedup vs baseline: 3.3176x; 1.3820x over previous
#include <cuda_runtime.h>
#include <cuda_fp16.h>
#include <cstdint>

#define Bv   2
#define Hv   16
#define Sv   2048
#define DKv  64
#define BHv  32
#define BM   64
#define BN   64
#define NITER (Sv/BN)
#define SCALE2 0.18033688011112042f   // (1/8)*log2(e)

#define NELEM ((size_t)BHv * Sv * DKv)   // 4,194,304

__device__ __align__(16) __half g_Qa[NELEM];
__device__ __align__(16) __half g_Qb[NELEM];
__device__ __align__(16) __half g_Ka[NELEM];
__device__ __align__(16) __half g_Kb[NELEM];
__device__ __align__(16) __half g_Vh[NELEM];
__device__ __align__(16) __half g_Vl[NELEM];

__device__ __forceinline__ uint32_t smem_u32(const void* p) {
    uint32_t a;
    asm("{ .reg .u64 t; cvta.to.shared.u64 t, %1; cvt.u32.u64 %0, t; }" : "=r"(a) : "l"(p));
    return a;
}
__device__ __forceinline__ void mma16816(float* d, const uint32_t* a, uint32_t b0, uint32_t b1) {
    asm volatile("mma.sync.aligned.m16n8k16.row.col.f32.f16.f16.f32 "
        "{%0,%1,%2,%3}, {%4,%5,%6,%7}, {%8,%9}, {%0,%1,%2,%3};"
        : "+f"(d[0]), "+f"(d[1]), "+f"(d[2]), "+f"(d[3])
        : "r"(a[0]), "r"(a[1]), "r"(a[2]), "r"(a[3]), "r"(b0), "r"(b1));
}
__device__ __forceinline__ void ldsm2(uint32_t& x, uint32_t& y, uint32_t addr) {
    asm volatile("ldmatrix.sync.aligned.m8n8.x2.shared.b16 {%0,%1}, [%2];"
                 : "=r"(x), "=r"(y) : "r"(addr));
}
__device__ __forceinline__ void ldsm2t(uint32_t& x, uint32_t& y, uint32_t addr) {
    asm volatile("ldmatrix.sync.aligned.m8n8.x2.trans.shared.b16 {%0,%1}, [%2];"
                 : "=r"(x), "=r"(y) : "r"(addr));
}
// pack two floats into f16x2: low = lo, high = hi
__device__ __forceinline__ uint32_t pack_h(float hi, float lo) {
    uint32_t r;
    asm("cvt.rn.f16x2.f32 %0, %1, %2;" : "=r"(r) : "f"(hi), "f"(lo));
    return r;
}
#define CPA(dst, src) asm volatile("cp.async.cg.shared.global [%0], [%1], 16;" :: "r"(dst), "l"(src) : "memory")

// p = (u>0) ? 2^u : 0 with u = s*SCALE2*m. Pure FMA-pipe exp (no MUFU).
__device__ __forceinline__ float pexp(float s, float m) {
    float u = s * SCALE2 * m;
    float t = u + 12582912.0f;
    int   n = (__float_as_int(t) - 0x4B400000 + 127) << 23;
    float f = u - (t - 12582912.0f);
    float p = 1.3343e-3f;
    p = fmaf(p, f, 9.6181e-3f);
    p = fmaf(p, f, 5.55041e-2f);
    p = fmaf(p, f, 2.40226507e-1f);
    p = fmaf(p, f, 6.93147182e-1f);
    p = fmaf(p, f, 1.0f);
    p *= __int_as_float(n);
    return (u > 0.0f) ? p : 0.0f;
}

// ---- prep: split Q/K/V 2-way fp16; K/V chunk-swizzled for ldmatrix ----
__global__ __launch_bounds__(256) void prep(const float* __restrict__ Q,
                                            const float* __restrict__ K,
                                            const float* __restrict__ V) {
    const uint32_t g = blockIdx.x * 256 + threadIdx.x;   // 16B-chunk index (8 halves)
    const uint32_t s = (g >> 3) & (Sv - 1);              // source row (64 halves = 8 chunks)
    const int which = blockIdx.y;                         // 0:Q 1:K 2:V
    const float* src = which == 0 ? Q : which == 1 ? K : V;
    const float4 v0 = ((const float4*)src)[g * 2 + 0];
    const float4 v1 = ((const float4*)src)[g * 2 + 1];
    const float x[8] = {v0.x, v0.y, v0.z, v0.w, v1.x, v1.y, v1.z, v1.w};
    const uint32_t og = (which == 0) ? g : ((g & ~7u) | ((g & 7u) ^ (s & 7u)));

    uint4 ua, ub;
    __half* A = (__half*)&ua;
    __half* B = (__half*)&ub;
#pragma unroll
    for (int e = 0; e < 8; e++) {
        __half a = __float2half_rn(x[e]);
        A[e] = a;
        B[e] = __float2half_rn(x[e] - __half2float(a));
    }
    if (which == 0)      { ((uint4*)g_Qa)[og] = ua; ((uint4*)g_Qb)[og] = ub; }
    else if (which == 1) { ((uint4*)g_Ka)[og] = ua; ((uint4*)g_Kb)[og] = ub; }
    else                 { ((uint4*)g_Vh)[og] = ua; ((uint4*)g_Vl)[og] = ub; }
}

// ---- main: register-MMA flash attention, fp16 2-way splits ----
__global__ __launch_bounds__(128, 3)
void sdp_mma(const float* __restrict__ Mask, float* __restrict__ Out) {
    extern __shared__ char smem[];
    const uint32_t sbase = smem_u32(smem);

    const int tid  = threadIdx.x;
    const int lane = tid & 31, warp = tid >> 5;
    const int bh = blockIdx.y, q0 = blockIdx.x * BM, b = bh >> 4;
    const int lq  = lane >> 2;            // 0..7
    const int lc2 = (lane & 3) * 2;       // 0,2,4,6
    const int r1 = q0 + warp * 16 + lq, r2 = r1 + 8;

    // --- Q fragments (2 splits), loaded once from gmem ---
    uint32_t qf[2][4][4];
    {
        const __half* qs[2] = {g_Qa, g_Qb};
#pragma unroll
        for (int sp = 0; sp < 2; sp++)
#pragma unroll
            for (int c = 0; c < 4; c++)
#pragma unroll
                for (int r = 0; r < 4; r++) {
                    int m = (r & 1) ? r2 : r1;
                    int k = c * 16 + ((r >> 1) << 3) + lc2;
                    qf[sp][c][r] = *(const uint32_t*)(qs[sp] + ((size_t)bh * Sv + m) * DKv + k);
                }
    }

    float O[8][4];
#pragma unroll
    for (int j = 0; j < 8; j++)
#pragma unroll
        for (int e = 0; e < 4; e++) O[j][e] = 0.0f;
    float lacc0 = 0.0f, lacc1 = 0.0f;

    const float* mp1 = Mask + ((size_t)b * Sv + r1) * Sv + lc2;
    const float* mp2 = Mask + ((size_t)b * Sv + r2) * Sv + lc2;

    const size_t gbyte0 = (size_t)(bh * Sv) * 128;   // fp16 row = 128 bytes
    const char* garr[4] = {(const char*)g_Ka + gbyte0, (const char*)g_Kb + gbyte0,
                           (const char*)g_Vh + gbyte0, (const char*)g_Vl + gbyte0};

    // prologue: tile 0 -> buf 0  (4 arrays x 8KB)
#pragma unroll
    for (int a = 0; a < 4; a++)
#pragma unroll
        for (int i = 0; i < 4; i++) {
            uint32_t off = (uint32_t)(tid + i * 128) * 16;
            CPA(sbase + a * 8192 + off, garr[a] + off);
        }
    asm volatile("cp.async.commit_group;" ::: "memory");

    for (int t = 0; t < NITER; t++) {
        const int buf = t & 1;
        if (t + 1 < NITER) {
            const uint32_t sb = sbase + (buf ^ 1) * 32768;
            const size_t go = (size_t)(t + 1) * 8192;
#pragma unroll
            for (int a = 0; a < 4; a++)
#pragma unroll
                for (int i = 0; i < 4; i++) {
                    uint32_t off = (uint32_t)(tid + i * 128) * 16;
                    CPA(sb + a * 8192 + off, garr[a] + go + off);
                }
            asm volatile("cp.async.commit_group;" ::: "memory");
            asm volatile("cp.async.wait_group 1;" ::: "memory");
        } else {
            asm volatile("cp.async.wait_group 0;" ::: "memory");
        }
        __syncthreads();

        const uint32_t sK = sbase + buf * 32768;
        const uint32_t sV = sK + 16384;

        // ---- S = Q K^T via 3 split products (aa, ba, ab) ----
        float S[8][4];
#pragma unroll
        for (int j = 0; j < 8; j++)
#pragma unroll
            for (int e = 0; e < 4; e++) S[j][e] = 0.0f;

#pragma unroll
        for (int c = 0; c < 4; c++) {
            const int rowk = (lane & 7);
            const int chk  = 2 * c + ((lane >> 3) & 1);
#pragma unroll
            for (int j = 0; j < 8; j++) {
                const int row = 8 * j + rowk;
                const uint32_t off = (uint32_t)row * 128 + (uint32_t)((chk ^ (row & 7)) << 4);
                uint32_t ka0, ka1, kb0, kb1;
                ldsm2(ka0, ka1, sK + 0    + off);
                ldsm2(kb0, kb1, sK + 8192 + off);
                mma16816(S[j], qf[0][c], ka0, ka1);   // aa
                mma16816(S[j], qf[1][c], ka0, ka1);   // ba
                mma16816(S[j], qf[0][c], kb0, kb1);   // ab
            }
        }

        // ---- masked softmax (no row max needed: kept scores > 0, dead = 0) ----
        const float* m1 = mp1 + t * BN;
        const float* m2 = mp2 + t * BN;
        uint32_t aph[8][2], apl[8][2];
#pragma unroll
        for (int f = 0; f < 8; f++) {
            float2 mA = *(const float2*)(m1 + 8 * f);
            float2 mB = *(const float2*)(m2 + 8 * f);
            float p0 = pexp(S[f][0], mA.x);
            float p1 = pexp(S[f][1], mA.y);
            float p2 = pexp(S[f][2], mB.x);
            float p3 = pexp(S[f][3], mB.y);
            lacc0 += p0 + p1;
            lacc1 += p2 + p3;
            uint32_t h0 = pack_h(p1, p0);
            uint32_t h1 = pack_h(p3, p2);
            aph[f][0] = h0; aph[f][1] = h1;
            float2 f0 = __half22float2(*reinterpret_cast<__half2*>(&h0));
            float2 f1 = __half22float2(*reinterpret_cast<__half2*>(&h1));
            apl[f][0] = pack_h(p1 - f0.y, p0 - f0.x);
            apl[f][1] = pack_h(p3 - f1.y, p2 - f1.x);
        }

        // ---- O += P V via 3 split products (Phi*Vh, Plo*Vh, Phi*Vl) ----
#pragma unroll
        for (int c = 0; c < 4; c++) {
            uint32_t a_h[4] = {aph[2 * c][0], aph[2 * c][1], aph[2 * c + 1][0], aph[2 * c + 1][1]};
            uint32_t a_l[4] = {apl[2 * c][0], apl[2 * c][1], apl[2 * c + 1][0], apl[2 * c + 1][1]};
            const int rowv = 16 * c + (lane & 15);
#pragma unroll
            for (int j = 0; j < 8; j++) {
                const uint32_t offv = (uint32_t)rowv * 128 + (uint32_t)((j ^ (rowv & 7)) << 4);
                uint32_t vh0, vh1, vl0, vl1;
                ldsm2t(vh0, vh1, sV + 0    + offv);
                ldsm2t(vl0, vl1, sV + 8192 + offv);
                mma16816(O[j], a_h, vh0, vh1);
                mma16816(O[j], a_l, vh0, vh1);
                mma16816(O[j], a_h, vl0, vl1);
            }
        }
        __syncthreads();   // all warps done with buf before it is refilled
    }

    // ---- epilogue: quad-reduce row sums, normalize, store ----
    lacc0 += __shfl_xor_sync(0xffffffffu, lacc0, 1);
    lacc0 += __shfl_xor_sync(0xffffffffu, lacc0, 2);
    lacc1 += __shfl_xor_sync(0xffffffffu, lacc1, 1);
    lacc1 += __shfl_xor_sync(0xffffffffu, lacc1, 2);
    const float li1 = 1.0f / lacc0;
    const float li2 = 1.0f / lacc1;

    float* o1 = Out + ((size_t)bh * Sv + r1) * DKv + lc2;
    float* o2 = Out + ((size_t)bh * Sv + r2) * DKv + lc2;
#pragma unroll
    for (int j = 0; j < 8; j++) {
        float2 w1 = make_float2(O[j][0] * li1, O[j][1] * li1);
        float2 w2 = make_float2(O[j][2] * li2, O[j][3] * li2);
        *(float2*)(o1 + 8 * j) = w1;
        *(float2*)(o2 + 8 * j) = w2;
    }
}

extern "C" void kernel_launch(void* const* d_in, const int* in_sizes, int n_in,
                              void* d_out, int out_size) {
    const float* Q = (const float*)d_in[0];
    const float* K = (const float*)d_in[1];
    const float* V = (const float*)d_in[2];
    const float* M = (const float*)d_in[3];
    float* Out = (float*)d_out;

    prep<<<dim3((unsigned)(NELEM / 8 / 256), 3), 256>>>(Q, K, V);

    cudaFuncSetAttribute(sdp_mma, cudaFuncAttributeMaxDynamicSharedMemorySize, 65536);
    sdp_mma<<<dim3(Sv / BM, BHv), 128, 65536>>>(M, Out);
}

// round 6
// speedup vs baseline: 3.7065x; 1.1172x over previous
#include <cuda_runtime.h>
#include <cuda_fp16.h>
#include <cstdint>

#define Bv   2
#define Hv   16
#define Sv   2048
#define DKv  64
#define BHv  32
#define BM   64
#define BN   64
#define NITER (Sv/BN)
#define SCALE2 0.18033688011112042f   // (1/8)*log2(e)

#define NELEM ((size_t)BHv * Sv * DKv)   // 4,194,304

__device__ __align__(16) __half g_Qa[NELEM];
__device__ __align__(16) __half g_Qb[NELEM];
__device__ __align__(16) __half g_Ka[NELEM];
__device__ __align__(16) __half g_Kb[NELEM];
__device__ __align__(16) __half g_Vh[NELEM];

__device__ __forceinline__ uint32_t smem_u32(const void* p) {
    uint32_t a;
    asm("{ .reg .u64 t; cvta.to.shared.u64 t, %1; cvt.u32.u64 %0, t; }" : "=r"(a) : "l"(p));
    return a;
}
__device__ __forceinline__ void mma16816(float* d, const uint32_t* a, uint32_t b0, uint32_t b1) {
    asm volatile("mma.sync.aligned.m16n8k16.row.col.f32.f16.f16.f32 "
        "{%0,%1,%2,%3}, {%4,%5,%6,%7}, {%8,%9}, {%0,%1,%2,%3};"
        : "+f"(d[0]), "+f"(d[1]), "+f"(d[2]), "+f"(d[3])
        : "r"(a[0]), "r"(a[1]), "r"(a[2]), "r"(a[3]), "r"(b0), "r"(b1));
}
// x4: four independent 8x8 matrices, one per 8-lane address group
__device__ __forceinline__ void ldsm4(uint32_t& a, uint32_t& b, uint32_t& c, uint32_t& d, uint32_t addr) {
    asm volatile("ldmatrix.sync.aligned.m8n8.x4.shared.b16 {%0,%1,%2,%3}, [%4];"
                 : "=r"(a), "=r"(b), "=r"(c), "=r"(d) : "r"(addr));
}
__device__ __forceinline__ void ldsm4t(uint32_t& a, uint32_t& b, uint32_t& c, uint32_t& d, uint32_t addr) {
    asm volatile("ldmatrix.sync.aligned.m8n8.x4.trans.shared.b16 {%0,%1,%2,%3}, [%4];"
                 : "=r"(a), "=r"(b), "=r"(c), "=r"(d) : "r"(addr));
}
__device__ __forceinline__ uint32_t pack_h(float hi, float lo) {
    uint32_t r;
    asm("cvt.rn.f16x2.f32 %0, %1, %2;" : "=r"(r) : "f"(hi), "f"(lo));
    return r;
}
#define CPA(dst, src) asm volatile("cp.async.cg.shared.global [%0], [%1], 16;" :: "r"(dst), "l"(src) : "memory")

// p = (u>0) ? 2^u : 0 with u = s*SCALE2*m. Pure FMA-pipe exp (no MUFU).
__device__ __forceinline__ float pexp(float s, float m) {
    float u = s * SCALE2 * m;
    float t = u + 12582912.0f;
    int   n = (__float_as_int(t) - 0x4B400000 + 127) << 23;
    float f = u - (t - 12582912.0f);
    float p = 1.3343e-3f;
    p = fmaf(p, f, 9.6181e-3f);
    p = fmaf(p, f, 5.55041e-2f);
    p = fmaf(p, f, 2.40226507e-1f);
    p = fmaf(p, f, 6.93147182e-1f);
    p = fmaf(p, f, 1.0f);
    p *= __int_as_float(n);
    return (u > 0.0f) ? p : 0.0f;
}

// ---- prep: split Q/K 2-way fp16, V single fp16; K/V chunk-swizzled for ldmatrix ----
__global__ __launch_bounds__(256) void prep(const float* __restrict__ Q,
                                            const float* __restrict__ K,
                                            const float* __restrict__ V) {
    const uint32_t g = blockIdx.x * 256 + threadIdx.x;   // 16B-chunk index (8 halves)
    const uint32_t s = (g >> 3) & (Sv - 1);              // source row
    const int which = blockIdx.y;                         // 0:Q 1:K 2:V
    const float* src = which == 0 ? Q : which == 1 ? K : V;
    const float4 v0 = ((const float4*)src)[g * 2 + 0];
    const float4 v1 = ((const float4*)src)[g * 2 + 1];
    const float x[8] = {v0.x, v0.y, v0.z, v0.w, v1.x, v1.y, v1.z, v1.w};
    const uint32_t og = (which == 0) ? g : ((g & ~7u) | ((g & 7u) ^ (s & 7u)));

    uint4 ua, ub;
    __half* A = (__half*)&ua;
    __half* B = (__half*)&ub;
#pragma unroll
    for (int e = 0; e < 8; e++) {
        __half a = __float2half_rn(x[e]);
        A[e] = a;
        B[e] = __float2half_rn(x[e] - __half2float(a));
    }
    if (which == 0)      { ((uint4*)g_Qa)[og] = ua; ((uint4*)g_Qb)[og] = ub; }
    else if (which == 1) { ((uint4*)g_Ka)[og] = ua; ((uint4*)g_Kb)[og] = ub; }
    else                 { ((uint4*)g_Vh)[og] = ua; }
}

// ---- main: register-MMA flash attention, 4 MMA products ----
__global__ __launch_bounds__(128, 3)
void sdp_mma(const float* __restrict__ Mask, float* __restrict__ Out) {
    extern __shared__ char smem[];
    const uint32_t sbase = smem_u32(smem);

    const int tid  = threadIdx.x;
    const int lane = tid & 31, warp = tid >> 5;
    const int bh = blockIdx.y, q0 = blockIdx.x * BM, b = bh >> 4;
    const int lq  = lane >> 2;            // 0..7
    const int lc2 = (lane & 3) * 2;       // 0,2,4,6
    const int r1 = q0 + warp * 16 + lq, r2 = r1 + 8;

    // --- Q fragments (2 splits), loaded once from gmem ---
    uint32_t qf[2][4][4];
    {
        const __half* qs[2] = {g_Qa, g_Qb};
#pragma unroll
        for (int sp = 0; sp < 2; sp++)
#pragma unroll
            for (int c = 0; c < 4; c++)
#pragma unroll
                for (int r = 0; r < 4; r++) {
                    int m = (r & 1) ? r2 : r1;
                    int k = c * 16 + ((r >> 1) << 3) + lc2;
                    qf[sp][c][r] = *(const uint32_t*)(qs[sp] + ((size_t)bh * Sv + m) * DKv + k);
                }
    }

    float O[8][4];
#pragma unroll
    for (int j = 0; j < 8; j++)
#pragma unroll
        for (int e = 0; e < 4; e++) O[j][e] = 0.0f;
    float lacc0 = 0.0f, lacc1 = 0.0f;

    const float* mp1 = Mask + ((size_t)b * Sv + r1) * Sv + lc2;
    const float* mp2 = Mask + ((size_t)b * Sv + r2) * Sv + lc2;

    const size_t gbyte0 = (size_t)(bh * Sv) * 128;   // fp16 row = 128 bytes
    const char* garr[3] = {(const char*)g_Ka + gbyte0, (const char*)g_Kb + gbyte0,
                           (const char*)g_Vh + gbyte0};

    // prologue: tile 0 -> buf 0  (3 arrays x 8KB)
#pragma unroll
    for (int a = 0; a < 3; a++)
#pragma unroll
        for (int i = 0; i < 4; i++) {
            uint32_t off = (uint32_t)(tid + i * 128) * 16;
            CPA(sbase + a * 8192 + off, garr[a] + off);
        }
    asm volatile("cp.async.commit_group;" ::: "memory");

    for (int t = 0; t < NITER; t++) {
        const int buf = t & 1;
        if (t + 1 < NITER) {
            const uint32_t sb = sbase + (buf ^ 1) * 24576;
            const size_t go = (size_t)(t + 1) * 8192;
#pragma unroll
            for (int a = 0; a < 3; a++)
#pragma unroll
                for (int i = 0; i < 4; i++) {
                    uint32_t off = (uint32_t)(tid + i * 128) * 16;
                    CPA(sb + a * 8192 + off, garr[a] + go + off);
                }
            asm volatile("cp.async.commit_group;" ::: "memory");
            asm volatile("cp.async.wait_group 1;" ::: "memory");
        } else {
            asm volatile("cp.async.wait_group 0;" ::: "memory");
        }
        __syncthreads();

        const uint32_t sK = sbase + buf * 24576;     // Ka @ +0, Kb @ +8192
        const uint32_t sV = sK + 16384;              // Vh

        // ---- S = Q K^T via 3 split products (aa, ba, ab) ----
        // one ldsm4: lanes 0-15 -> Ka fragment, lanes 16-31 -> Kb fragment
        float S[8][4];
#pragma unroll
        for (int j = 0; j < 8; j++)
#pragma unroll
            for (int e = 0; e < 4; e++) S[j][e] = 0.0f;

        const int rowk = lane & 7;
        const int half = (lane >> 3) & 1;
        const uint32_t karr = (uint32_t)(lane >> 4) * 8192;
#pragma unroll
        for (int c = 0; c < 4; c++) {
            const int chk = 2 * c + half;
#pragma unroll
            for (int j = 0; j < 8; j++) {
                const int row = 8 * j + rowk;
                const uint32_t off = karr + (uint32_t)row * 128 + (uint32_t)((chk ^ (row & 7)) << 4);
                uint32_t ka0, ka1, kb0, kb1;
                ldsm4(ka0, ka1, kb0, kb1, sK + off);
                mma16816(S[j], qf[0][c], ka0, ka1);   // aa
                mma16816(S[j], qf[1][c], ka0, ka1);   // ba
                mma16816(S[j], qf[0][c], kb0, kb1);   // ab
            }
        }

        // ---- masked softmax (no row max: kept scores > 0, dead = 0) ----
        const float* m1 = mp1 + t * BN;
        const float* m2 = mp2 + t * BN;
        uint32_t aph[8][2];
#pragma unroll
        for (int f = 0; f < 8; f++) {
            float2 mA = *(const float2*)(m1 + 8 * f);
            float2 mB = *(const float2*)(m2 + 8 * f);
            float p0 = pexp(S[f][0], mA.x);
            float p1 = pexp(S[f][1], mA.y);
            float p2 = pexp(S[f][2], mB.x);
            float p3 = pexp(S[f][3], mB.y);
            lacc0 += p0 + p1;
            lacc1 += p2 + p3;
            aph[f][0] = pack_h(p1, p0);
            aph[f][1] = pack_h(p3, p2);
        }

        // ---- O += P V, single product; ldsm4t covers two n-chunks at once ----
        const int rowv16 = lane & 15;
        const uint32_t jsel = (uint32_t)(lane >> 4);
#pragma unroll
        for (int c = 0; c < 4; c++) {
            uint32_t a_h[4] = {aph[2 * c][0], aph[2 * c][1], aph[2 * c + 1][0], aph[2 * c + 1][1]};
            const int rowv = 16 * c + rowv16;
#pragma unroll
            for (int jj = 0; jj < 4; jj++) {
                const uint32_t j0 = 2 * jj;
                const uint32_t offv = (uint32_t)rowv * 128 + (uint32_t)(((j0 + jsel) ^ (rowv & 7)) << 4);
                uint32_t v00, v01, v10, v11;
                ldsm4t(v00, v01, v10, v11, sV + offv);
                mma16816(O[j0],     a_h, v00, v01);
                mma16816(O[j0 + 1], a_h, v10, v11);
            }
        }
        __syncthreads();   // all warps done with buf before refill
    }

    // ---- epilogue: quad-reduce row sums, normalize, store ----
    lacc0 += __shfl_xor_sync(0xffffffffu, lacc0, 1);
    lacc0 += __shfl_xor_sync(0xffffffffu, lacc0, 2);
    lacc1 += __shfl_xor_sync(0xffffffffu, lacc1, 1);
    lacc1 += __shfl_xor_sync(0xffffffffu, lacc1, 2);
    const float li1 = 1.0f / lacc0;
    const float li2 = 1.0f / lacc1;

    float* o1 = Out + ((size_t)bh * Sv + r1) * DKv + lc2;
    float* o2 = Out + ((size_t)bh * Sv + r2) * DKv + lc2;
#pragma unroll
    for (int j = 0; j < 8; j++) {
        float2 w1 = make_float2(O[j][0] * li1, O[j][1] * li1);
        float2 w2 = make_float2(O[j][2] * li2, O[j][3] * li2);
        *(float2*)(o1 + 8 * j) = w1;
        *(float2*)(o2 + 8 * j) = w2;
    }
}

extern "C" void kernel_launch(void* const* d_in, const int* in_sizes, int n_in,
                              void* d_out, int out_size) {
    const float* Q = (const float*)d_in[0];
    const float* K = (const float*)d_in[1];
    const float* V = (const float*)d_in[2];
    const float* M = (const float*)d_in[3];
    float* Out = (float*)d_out;

    prep<<<dim3((unsigned)(NELEM / 8 / 256), 3), 256>>>(Q, K, V);

    cudaFuncSetAttribute(sdp_mma, cudaFuncAttributeMaxDynamicSharedMemorySize, 49152);
    sdp_mma<<<dim3(Sv / BM, BHv), 128, 49152>>>(M, Out);
}

// round 7
// speedup vs baseline: 4.2608x; 1.1496x over previous
#include <cuda_runtime.h>
#include <cuda_fp16.h>
#include <cstdint>

#define Bv   2
#define Hv   16
#define Sv   2048
#define DKv  64
#define BHv  32
#define BM   64
#define BN   64
#define NITER (Sv/BN)
#define SCALE2 0.18033688011112042f   // (1/8)*log2(e)

#define NELEM ((size_t)BHv * Sv * DKv)   // 4,194,304
#define NMASKW ((size_t)Bv * Sv * Sv / 32)  // 262,144 uint32

__device__ __align__(16) __half g_Qa[NELEM];
__device__ __align__(16) __half g_Qb[NELEM];
__device__ __align__(16) __half g_Ka[NELEM];
__device__ __align__(16) __half g_Kb[NELEM];
__device__ __align__(16) __half g_Vh[NELEM];
__device__ __align__(16) uint32_t g_Mb[NMASKW];

__device__ __forceinline__ uint32_t smem_u32(const void* p) {
    uint32_t a;
    asm("{ .reg .u64 t; cvta.to.shared.u64 t, %1; cvt.u32.u64 %0, t; }" : "=r"(a) : "l"(p));
    return a;
}
__device__ __forceinline__ void mma16816(float* d, const uint32_t* a, uint32_t b0, uint32_t b1) {
    asm volatile("mma.sync.aligned.m16n8k16.row.col.f32.f16.f16.f32 "
        "{%0,%1,%2,%3}, {%4,%5,%6,%7}, {%8,%9}, {%0,%1,%2,%3};"
        : "+f"(d[0]), "+f"(d[1]), "+f"(d[2]), "+f"(d[3])
        : "r"(a[0]), "r"(a[1]), "r"(a[2]), "r"(a[3]), "r"(b0), "r"(b1));
}
__device__ __forceinline__ void ldsm4(uint32_t& a, uint32_t& b, uint32_t& c, uint32_t& d, uint32_t addr) {
    asm volatile("ldmatrix.sync.aligned.m8n8.x4.shared.b16 {%0,%1,%2,%3}, [%4];"
                 : "=r"(a), "=r"(b), "=r"(c), "=r"(d) : "r"(addr));
}
__device__ __forceinline__ void ldsm4t(uint32_t& a, uint32_t& b, uint32_t& c, uint32_t& d, uint32_t addr) {
    asm volatile("ldmatrix.sync.aligned.m8n8.x4.trans.shared.b16 {%0,%1,%2,%3}, [%4];"
                 : "=r"(a), "=r"(b), "=r"(c), "=r"(d) : "r"(addr));
}
__device__ __forceinline__ uint32_t pack_h(float hi, float lo) {
    uint32_t r;
    asm("cvt.rn.f16x2.f32 %0, %1, %2;" : "=r"(r) : "f"(hi), "f"(lo));
    return r;
}
#define CPA(dst, src) asm volatile("cp.async.cg.shared.global [%0], [%1], 16;" :: "r"(dst), "l"(src) : "memory")

// u is already scale*log2e*dot (Q pre-scaled). p = (m && u>0) ? 2^u : 0.
__device__ __forceinline__ float pexpb(float u, unsigned m) {
    float t = u + 12582912.0f;
    int   n = (__float_as_int(t) - 0x4B400000 + 127) << 23;
    float f = u - (t - 12582912.0f);
    float p = 1.3343e-3f;
    p = fmaf(p, f, 9.6181e-3f);
    p = fmaf(p, f, 5.55041e-2f);
    p = fmaf(p, f, 2.40226507e-1f);
    p = fmaf(p, f, 6.93147182e-1f);
    p = fmaf(p, f, 1.0f);
    p *= __int_as_float(n);
    return ((u > 0.0f) && (m != 0u)) ? p : 0.0f;
}

// ---- prep: split Q (pre-scaled) / K 2-way fp16, V single; K/V chunk-swizzled ----
__global__ __launch_bounds__(256) void prep(const float* __restrict__ Q,
                                            const float* __restrict__ K,
                                            const float* __restrict__ V) {
    const uint32_t g = blockIdx.x * 256 + threadIdx.x;   // 16B-chunk index (8 halves)
    const uint32_t s = (g >> 3) & (Sv - 1);
    const int which = blockIdx.y;                         // 0:Q 1:K 2:V
    const float* src = which == 0 ? Q : which == 1 ? K : V;
    const float4 v0 = ((const float4*)src)[g * 2 + 0];
    const float4 v1 = ((const float4*)src)[g * 2 + 1];
    float x[8] = {v0.x, v0.y, v0.z, v0.w, v1.x, v1.y, v1.z, v1.w};
    if (which == 0) {
#pragma unroll
        for (int e = 0; e < 8; e++) x[e] *= SCALE2;       // fold scale*log2e into Q
    }
    const uint32_t og = (which == 0) ? g : ((g & ~7u) | ((g & 7u) ^ (s & 7u)));

    uint4 ua, ub;
    __half* A = (__half*)&ua;
    __half* B = (__half*)&ub;
#pragma unroll
    for (int e = 0; e < 8; e++) {
        __half a = __float2half_rn(x[e]);
        A[e] = a;
        B[e] = __float2half_rn(x[e] - __half2float(a));
    }
    if (which == 0)      { ((uint4*)g_Qa)[og] = ua; ((uint4*)g_Qb)[og] = ub; }
    else if (which == 1) { ((uint4*)g_Ka)[og] = ua; ((uint4*)g_Kb)[og] = ub; }
    else                 { ((uint4*)g_Vh)[og] = ua; }
}

// ---- prep: pack mask floats (0.0/1.0) into bits, 32 keys per uint32 ----
__global__ __launch_bounds__(256) void prep_mask(const float* __restrict__ M) {
    const uint32_t w = blockIdx.x * 256 + threadIdx.x;    // word index
    const float4* src = (const float4*)M + (size_t)w * 8;
    uint32_t bits = 0;
#pragma unroll
    for (int i = 0; i < 8; i++) {
        float4 v = src[i];
        bits |= (v.x != 0.0f ? 1u : 0u) << (4 * i + 0);
        bits |= (v.y != 0.0f ? 1u : 0u) << (4 * i + 1);
        bits |= (v.z != 0.0f ? 1u : 0u) << (4 * i + 2);
        bits |= (v.w != 0.0f ? 1u : 0u) << (4 * i + 3);
    }
    g_Mb[w] = bits;
}

// ---- main: register-MMA flash attention, 4 MMA products, bitmask, 3 buffers ----
__global__ __launch_bounds__(128, 3)
void sdp_mma(float* __restrict__ Out) {
    extern __shared__ char smem[];
    const uint32_t sbase = smem_u32(smem);

    const int tid  = threadIdx.x;
    const int lane = tid & 31, warp = tid >> 5;
    const int bh = blockIdx.y, q0 = blockIdx.x * BM, b = bh >> 4;
    const int lq  = lane >> 2;
    const int lc2 = (lane & 3) * 2;
    const int r1 = q0 + warp * 16 + lq, r2 = r1 + 8;

    // Q fragments (2 splits), loaded once
    uint32_t qf[2][4][4];
    {
        const __half* qs[2] = {g_Qa, g_Qb};
#pragma unroll
        for (int sp = 0; sp < 2; sp++)
#pragma unroll
            for (int c = 0; c < 4; c++)
#pragma unroll
                for (int r = 0; r < 4; r++) {
                    int m = (r & 1) ? r2 : r1;
                    int k = c * 16 + ((r >> 1) << 3) + lc2;
                    qf[sp][c][r] = *(const uint32_t*)(qs[sp] + ((size_t)bh * Sv + m) * DKv + k);
                }
    }

    float O[8][4];
#pragma unroll
    for (int j = 0; j < 8; j++)
#pragma unroll
        for (int e = 0; e < 4; e++) O[j][e] = 0.0f;
    float lacc0 = 0.0f, lacc1 = 0.0f;

    // bitmask rows: 32 uint64 per row (one per tile)
    const uint64_t* mb1 = (const uint64_t*)g_Mb + (((size_t)b * Sv + r1) << 5);
    const uint64_t* mb2 = (const uint64_t*)g_Mb + (((size_t)b * Sv + r2) << 5);

    const size_t gbyte0 = (size_t)(bh * Sv) * 128;
    const char* garr[3] = {(const char*)g_Ka + gbyte0, (const char*)g_Kb + gbyte0,
                           (const char*)g_Vh + gbyte0};

    // prologue: tiles 0 and 1 into buffers 0 and 1
#pragma unroll
    for (int a = 0; a < 3; a++)
#pragma unroll
        for (int i = 0; i < 4; i++) {
            uint32_t off = (uint32_t)(tid + i * 128) * 16;
            CPA(sbase + a * 8192 + off, garr[a] + off);
        }
    asm volatile("cp.async.commit_group;" ::: "memory");
#pragma unroll
    for (int a = 0; a < 3; a++)
#pragma unroll
        for (int i = 0; i < 4; i++) {
            uint32_t off = (uint32_t)(tid + i * 128) * 16;
            CPA(sbase + 24576 + a * 8192 + off, garr[a] + 8192 + off);
        }
    asm volatile("cp.async.commit_group;" ::: "memory");

    int cur = 0, pf = 2;
    for (int t = 0; t < NITER; t++) {
        if (t == NITER - 1) asm volatile("cp.async.wait_group 0;" ::: "memory");
        else                asm volatile("cp.async.wait_group 1;" ::: "memory");
        __syncthreads();   // tile t ready; all warps done with tile t-1's buffer

        if (t + 2 < NITER) {
            const uint32_t sb = sbase + pf * 24576;
            const size_t go = (size_t)(t + 2) * 8192;
#pragma unroll
            for (int a = 0; a < 3; a++)
#pragma unroll
                for (int i = 0; i < 4; i++) {
                    uint32_t off = (uint32_t)(tid + i * 128) * 16;
                    CPA(sb + a * 8192 + off, garr[a] + go + off);
                }
            asm volatile("cp.async.commit_group;" ::: "memory");
        }

        const uint32_t sK = sbase + cur * 24576;   // Ka @ +0, Kb @ +8192
        const uint32_t sV = sK + 16384;            // Vh

        // ---- S = Q K^T via 3 split products ----
        float S[8][4];
#pragma unroll
        for (int j = 0; j < 8; j++)
#pragma unroll
            for (int e = 0; e < 4; e++) S[j][e] = 0.0f;

        const int rowk = lane & 7;
        const int half = (lane >> 3) & 1;
        const uint32_t karr = (uint32_t)(lane >> 4) * 8192;
#pragma unroll
        for (int c = 0; c < 4; c++) {
            const int chk = 2 * c + half;
#pragma unroll
            for (int j = 0; j < 8; j++) {
                const int row = 8 * j + rowk;
                const uint32_t off = karr + (uint32_t)row * 128 + (uint32_t)((chk ^ (row & 7)) << 4);
                uint32_t ka0, ka1, kb0, kb1;
                ldsm4(ka0, ka1, kb0, kb1, sK + off);
                mma16816(S[j], qf[0][c], ka0, ka1);
                mma16816(S[j], qf[1][c], ka0, ka1);
                mma16816(S[j], qf[0][c], kb0, kb1);
            }
        }

        // ---- masked softmax via bit tests ----
        const uint64_t s1 = mb1[t] >> lc2;
        const uint64_t s2 = mb2[t] >> lc2;
        uint32_t aph[8][2];
#pragma unroll
        for (int f = 0; f < 8; f++) {
            const unsigned w1 = (unsigned)(s1 >> (8 * f));
            const unsigned w2 = (unsigned)(s2 >> (8 * f));
            float p0 = pexpb(S[f][0], w1 & 1u);
            float p1 = pexpb(S[f][1], w1 & 2u);
            float p2 = pexpb(S[f][2], w2 & 1u);
            float p3 = pexpb(S[f][3], w2 & 2u);
            lacc0 += p0 + p1;
            lacc1 += p2 + p3;
            aph[f][0] = pack_h(p1, p0);
            aph[f][1] = pack_h(p3, p2);
        }

        // ---- O += P V, single product ----
        const int rowv16 = lane & 15;
        const uint32_t jsel = (uint32_t)(lane >> 4);
#pragma unroll
        for (int c = 0; c < 4; c++) {
            uint32_t a_h[4] = {aph[2 * c][0], aph[2 * c][1], aph[2 * c + 1][0], aph[2 * c + 1][1]};
            const int rowv = 16 * c + rowv16;
#pragma unroll
            for (int jj = 0; jj < 4; jj++) {
                const uint32_t j0 = 2 * jj;
                const uint32_t offv = (uint32_t)rowv * 128 + (uint32_t)(((j0 + jsel) ^ (rowv & 7)) << 4);
                uint32_t v00, v01, v10, v11;
                ldsm4t(v00, v01, v10, v11, sV + offv);
                mma16816(O[j0],     a_h, v00, v01);
                mma16816(O[j0 + 1], a_h, v10, v11);
            }
        }

        cur = (cur == 2) ? 0 : cur + 1;
        pf  = (pf  == 2) ? 0 : pf  + 1;
    }

    // ---- epilogue ----
    lacc0 += __shfl_xor_sync(0xffffffffu, lacc0, 1);
    lacc0 += __shfl_xor_sync(0xffffffffu, lacc0, 2);
    lacc1 += __shfl_xor_sync(0xffffffffu, lacc1, 1);
    lacc1 += __shfl_xor_sync(0xffffffffu, lacc1, 2);
    const float li1 = 1.0f / lacc0;
    const float li2 = 1.0f / lacc1;

    float* o1 = Out + ((size_t)bh * Sv + r1) * DKv + lc2;
    float* o2 = Out + ((size_t)bh * Sv + r2) * DKv + lc2;
#pragma unroll
    for (int j = 0; j < 8; j++) {
        float2 w1 = make_float2(O[j][0] * li1, O[j][1] * li1);
        float2 w2 = make_float2(O[j][2] * li2, O[j][3] * li2);
        *(float2*)(o1 + 8 * j) = w1;
        *(float2*)(o2 + 8 * j) = w2;
    }
}

extern "C" void kernel_launch(void* const* d_in, const int* in_sizes, int n_in,
                              void* d_out, int out_size) {
    const float* Q = (const float*)d_in[0];
    const float* K = (const float*)d_in[1];
    const float* V = (const float*)d_in[2];
    const float* M = (const float*)d_in[3];
    float* Out = (float*)d_out;

    prep<<<dim3((unsigned)(NELEM / 8 / 256), 3), 256>>>(Q, K, V);
    prep_mask<<<(unsigned)(NMASKW / 256), 256>>>(M);

    cudaFuncSetAttribute(sdp_mma, cudaFuncAttributeMaxDynamicSharedMemorySize, 73728);
    sdp_mma<<<dim3(Sv / BM, BHv), 128, 73728>>>(Out);
}